// round 1
// baseline (speedup 1.0000x reference)
#include <cuda_runtime.h>
#include <math.h>

// Problem constants
#define NF   128          // frames
#define PP   576          // patches
#define DD   1536         // feature dim
#define LMq  4096         // LM
#define NQk  64           // NQ
#define NM1  127          // N-1
#define NC   8            // NUM_CUBES

// Scratch layout inside one big __device__ array (no allocations allowed)
#define OFF_MP    0
#define OFF_EMA   (NF*DD)
#define OFF_FEAT  (OFF_EMA  + NM1*DD)
#define OFF_XN    (OFF_FEAT + NM1*DD)
#define OFF_H     (OFF_XN   + NM1*DD)
#define OFF_POOL  (OFF_H    + NM1*DD)
#define OFF_Y     (OFF_POOL + NQk*DD)
#define SCRATCH_TOTAL (OFF_Y + 256)

__device__ float g_scratch[SCRATCH_TOTAL];
__device__ int   g_sel[NC + 1];

// ---------------------------------------------------------------------------
// Kernel 1: patch-mean  mp[n,d] = mean_p v[n,p,d]   (reads 453MB — HBM bound)
// grid = NF*3 blocks, 128 threads, float4 per thread (512 d per block)
// ---------------------------------------------------------------------------
__global__ void k_mp(const float* __restrict__ v, float* __restrict__ mp) {
    int b = blockIdx.x;
    int n = b / 3, c = b % 3;
    int d = c * 512 + threadIdx.x * 4;
    const float* base = v + (size_t)n * PP * DD + d;
    float ax = 0.f, ay = 0.f, az = 0.f, aw = 0.f;
#pragma unroll 4
    for (int p = 0; p < PP; p++) {
        float4 x = *reinterpret_cast<const float4*>(base + (size_t)p * DD);
        ax += x.x; ay += x.y; az += x.z; aw += x.w;
    }
    const float inv = 1.0f / (float)PP;
    float4 r = make_float4(ax * inv, ay * inv, az * inv, aw * inv);
    *reinterpret_cast<float4*>(&mp[n * DD + d]) = r;
}

// ---------------------------------------------------------------------------
// Kernel 2: momentum EMA over frame diffs (per-d independent scan)
// diffs[i] = mp[i+1]-mp[i]; ema[0]=diffs[0]; ema[i]=0.5*diffs[i]+0.5*ema[i-1]
// ---------------------------------------------------------------------------
__global__ void k_ema(const float* __restrict__ mp, float* __restrict__ ema) {
    int d = blockIdx.x * blockDim.x + threadIdx.x;
    float prev = mp[d];
    float cur  = mp[DD + d];
    float e = cur - prev;
    ema[d] = e;
    prev = cur;
    for (int i = 1; i < NM1; i++) {
        float nx = mp[(size_t)(i + 1) * DD + d];
        float diff = nx - prev;
        e = 0.5f * diff + 0.5f * e;
        ema[(size_t)i * DD + d] = e;
        prev = nx;
    }
}

// ---------------------------------------------------------------------------
// Bias init:  C[m, n] = bias[n]   (total = M*N elements)
// ---------------------------------------------------------------------------
__global__ void k_init_bias(float* __restrict__ C, const float* __restrict__ bias,
                            int total, int Nn) {
    int idx = blockIdx.x * blockDim.x + threadIdx.x;
    if (idx < total) C[idx] = bias[idx % Nn];
}

// ---------------------------------------------------------------------------
// Split-K fp32 GEMM:  C += A[M,K] @ B[K,N]   (atomicAdd epilogue)
// Tile 64x64, BK=16, 256 threads, 4x4 micro-tile, grid(N/64, ceil(M/64), S)
// ---------------------------------------------------------------------------
__global__ void k_gemm_splitk(const float* __restrict__ A, const float* __restrict__ B,
                              float* __restrict__ C, int M, int Nn, int K, int Kc) {
    __shared__ __align__(16) float As[16][68];
    __shared__ __align__(16) float Bs[16][64];
    int n0 = blockIdx.x * 64;
    int m0 = blockIdx.y * 64;
    int k0 = blockIdx.z * Kc;
    int kend = k0 + Kc; if (kend > K) kend = K;
    int tid = threadIdx.x;
    int tx = tid & 15, ty = tid >> 4;

    float acc[4][4];
#pragma unroll
    for (int i = 0; i < 4; i++)
#pragma unroll
        for (int j = 0; j < 4; j++) acc[i][j] = 0.f;

    for (int kb = k0; kb < kend; kb += 16) {
#pragma unroll
        for (int i = 0; i < 4; i++) {
            int l = tid + i * 256;          // 0..1023 over 64x16 A tile
            int ml = l >> 4, kl = l & 15;
            int m = m0 + ml;
            As[kl][ml] = (m < M) ? A[(size_t)m * K + kb + kl] : 0.f;
        }
#pragma unroll
        for (int i = 0; i < 4; i++) {
            int l = tid + i * 256;          // 0..1023 over 16x64 B tile
            int kl = l >> 6, nl = l & 63;
            Bs[kl][nl] = B[(size_t)(kb + kl) * Nn + n0 + nl];
        }
        __syncthreads();
#pragma unroll
        for (int kk = 0; kk < 16; kk++) {
            float4 a = *reinterpret_cast<const float4*>(&As[kk][ty * 4]);
            float4 bq = *reinterpret_cast<const float4*>(&Bs[kk][tx * 4]);
            float av[4] = {a.x, a.y, a.z, a.w};
            float bv[4] = {bq.x, bq.y, bq.z, bq.w};
#pragma unroll
            for (int i = 0; i < 4; i++)
#pragma unroll
                for (int j = 0; j < 4; j++) acc[i][j] += av[i] * bv[j];
        }
        __syncthreads();
    }
#pragma unroll
    for (int i = 0; i < 4; i++) {
        int m = m0 + ty * 4 + i;
        if (m < M) {
#pragma unroll
            for (int j = 0; j < 4; j++)
                atomicAdd(&C[(size_t)m * Nn + n0 + tx * 4 + j], acc[i][j]);
        }
    }
}

// ---------------------------------------------------------------------------
// LayerNorm per row (two-pass for numerical fidelity)
// ---------------------------------------------------------------------------
__global__ void k_ln(const float* __restrict__ X, float* __restrict__ Y,
                     const float* __restrict__ gam, const float* __restrict__ bet) {
    int m = blockIdx.x;
    const float* x = X + (size_t)m * DD;
    float* y = Y + (size_t)m * DD;
    __shared__ float red[32];
    __shared__ float s_mu, s_rstd;

    float s = 0.f;
    for (int d = threadIdx.x; d < DD; d += 256) s += x[d];
    for (int o = 16; o; o >>= 1) s += __shfl_down_sync(0xffffffffu, s, o);
    int w = threadIdx.x >> 5, lane = threadIdx.x & 31;
    if (lane == 0) red[w] = s;
    __syncthreads();
    if (threadIdx.x == 0) {
        float t = 0.f;
        for (int i = 0; i < 8; i++) t += red[i];
        s_mu = t / (float)DD;
    }
    __syncthreads();
    float mu = s_mu;

    float s2 = 0.f;
    for (int d = threadIdx.x; d < DD; d += 256) {
        float v = x[d] - mu; s2 += v * v;
    }
    for (int o = 16; o; o >>= 1) s2 += __shfl_down_sync(0xffffffffu, s2, o);
    if (lane == 0) red[w] = s2;
    __syncthreads();
    if (threadIdx.x == 0) {
        float t = 0.f;
        for (int i = 0; i < 8; i++) t += red[i];
        s_rstd = rsqrtf(t / (float)DD + 1e-5f);
    }
    __syncthreads();
    float rstd = s_rstd;

    for (int d = threadIdx.x; d < DD; d += 256)
        y[d] = (x[d] - mu) * rstd * gam[d] + bet[d];
}

// ---------------------------------------------------------------------------
// Exact GELU (erf form) in place
// ---------------------------------------------------------------------------
__global__ void k_gelu(float* __restrict__ X, int total) {
    int idx = blockIdx.x * blockDim.x + threadIdx.x;
    if (idx < total) {
        float x = X[idx];
        X[idx] = 0.5f * x * (1.f + erff(x * 0.70710678118654752440f));
    }
}

// ---------------------------------------------------------------------------
// Gate head: logits = h @ W2 + b2 ; write logits to out ; compute Gumbel y
// grid = 127 blocks, 128 threads
// ---------------------------------------------------------------------------
__global__ void k_gate(const float* __restrict__ H, const float* __restrict__ W2,
                       const float* __restrict__ b2, const float* __restrict__ gu,
                       float* __restrict__ out_gate, float* __restrict__ y) {
    int m = blockIdx.x;
    const float* h = H + (size_t)m * DD;
    float a0 = 0.f, a1 = 0.f;
    for (int k = threadIdx.x; k < DD; k += 128) {
        float hv = h[k];
        a0 += hv * W2[2 * k + 0];
        a1 += hv * W2[2 * k + 1];
    }
    for (int o = 16; o; o >>= 1) {
        a0 += __shfl_down_sync(0xffffffffu, a0, o);
        a1 += __shfl_down_sync(0xffffffffu, a1, o);
    }
    __shared__ float r0[4], r1[4];
    int w = threadIdx.x >> 5, lane = threadIdx.x & 31;
    if (lane == 0) { r0[w] = a0; r1[w] = a1; }
    __syncthreads();
    if (threadIdx.x == 0) {
        float l0 = r0[0] + r0[1] + r0[2] + r0[3] + b2[0];
        float l1 = r1[0] + r1[1] + r1[2] + r1[3] + b2[1];
        out_gate[2 * m + 0] = l0;
        out_gate[2 * m + 1] = l1;
        float u0 = gu[2 * m + 0], u1 = gu[2 * m + 1];
        float g0 = -logf(-logf(u0 + 1e-20f) + 1e-20f);
        float g1 = -logf(-logf(u1 + 1e-20f) + 1e-20f);
        float s0 = (l0 + 0.1f * g0) * 2.0f;   // /TEMP where TEMP=0.5
        float s1 = (l1 + 0.1f * g1) * 2.0f;
        y[m] = 1.0f / (1.0f + expf(s0 - s1)); // softmax[:,1]
    }
}

// ---------------------------------------------------------------------------
// Top-k (8 of 127, stable descending) + z_hard output + selected frame list
// ---------------------------------------------------------------------------
__global__ void k_topk(const float* __restrict__ y, float* __restrict__ out_z) {
    if (threadIdx.x != 0 || blockIdx.x != 0) return;
    float v[NM1];
    bool taken[NM1];
    for (int i = 0; i < NM1; i++) { v[i] = y[i]; taken[i] = false; }
    out_z[0] = 1.f;
    for (int i = 0; i < NM1; i++) out_z[i + 1] = 0.f;
    g_sel[0] = 0;
    for (int r = 0; r < NC; r++) {
        float best = -1e30f; int bi = 0;
        for (int i = 0; i < NM1; i++)
            if (!taken[i] && v[i] > best) { best = v[i]; bi = i; }
        taken[bi] = true;
        g_sel[r + 1] = bi + 1;
        out_z[bi + 1] = 1.f;
    }
}

// ---------------------------------------------------------------------------
// Pooled thumbnail features: pooled[q,d] = (1/(zsum*9)) * sum_{f in sel} sum_{p in group q} v
// zsum = 9 exactly (frame 0 + 8 selected). grid = NQ*3 blocks, 128 threads.
// ---------------------------------------------------------------------------
__global__ void k_pool(const float* __restrict__ v, float* __restrict__ pooled) {
    int b = blockIdx.x;
    int q = b / 3, c = b % 3;
    int d = c * 512 + threadIdx.x * 4;
    float ax = 0.f, ay = 0.f, az = 0.f, aw = 0.f;
    for (int s = 0; s <= NC; s++) {
        int f = g_sel[s];
        const float* base = v + ((size_t)f * PP + q * 9) * DD + d;
#pragma unroll
        for (int p = 0; p < 9; p++) {
            float4 x = *reinterpret_cast<const float4*>(base + (size_t)p * DD);
            ax += x.x; ay += x.y; az += x.z; aw += x.w;
        }
    }
    const float inv = 1.0f / 81.0f;   // / zsum(=9) / group(=9)
    float4 r = make_float4(ax * inv, ay * inv, az * inv, aw * inv);
    *reinterpret_cast<float4*>(&pooled[(size_t)q * DD + d]) = r;
}

// ---------------------------------------------------------------------------
// Launch
// ---------------------------------------------------------------------------
extern "C" void kernel_launch(void* const* d_in, const int* in_sizes, int n_in,
                              void* d_out, int out_size) {
    const float* v     = (const float*)d_in[0];
    const float* gu    = (const float*)d_in[1];
    const float* W_agg = (const float*)d_in[2];
    const float* b_agg = (const float*)d_in[3];
    const float* ln_g  = (const float*)d_in[4];
    const float* ln_b  = (const float*)d_in[5];
    const float* W1    = (const float*)d_in[6];
    const float* b1    = (const float*)d_in[7];
    const float* W2    = (const float*)d_in[8];
    const float* b2    = (const float*)d_in[9];
    const float* W_th  = (const float*)d_in[10];
    const float* b_th  = (const float*)d_in[11];

    float* out       = (float*)d_out;
    float* out_gate  = out;                       // [127,2]
    float* out_thumb = out + NM1 * 2;             // [64,4096]
    float* out_z     = out_thumb + NQk * LMq;     // [128]

    float* scr = nullptr;
    cudaGetSymbolAddress((void**)&scr, g_scratch);
    float* mp     = scr + OFF_MP;
    float* ema    = scr + OFF_EMA;
    float* feat   = scr + OFF_FEAT;
    float* xn     = scr + OFF_XN;
    float* h      = scr + OFF_H;
    float* pooled = scr + OFF_POOL;
    float* yv     = scr + OFF_Y;

    // Step 1+2 prologue: patch means, then EMA scan (linear ops commuted)
    k_mp<<<NF * 3, 128>>>(v, mp);
    k_ema<<<DD / 128, 128>>>(mp, ema);

    // feat = ema @ W_agg + b_agg   [127,1536]x[1536,1536]
    k_init_bias<<<(NM1 * DD + 255) / 256, 256>>>(feat, b_agg, NM1 * DD, DD);
    {
        dim3 grid(DD / 64, (NM1 + 63) / 64, 4);
        k_gemm_splitk<<<grid, 256>>>(ema, W_agg, feat, NM1, DD, DD, DD / 4);
    }

    // LayerNorm
    k_ln<<<NM1, 256>>>(feat, xn, ln_g, ln_b);

    // h = gelu(xn @ W1 + b1)
    k_init_bias<<<(NM1 * DD + 255) / 256, 256>>>(h, b1, NM1 * DD, DD);
    {
        dim3 grid(DD / 64, (NM1 + 63) / 64, 4);
        k_gemm_splitk<<<grid, 256>>>(xn, W1, h, NM1, DD, DD, DD / 4);
    }
    k_gelu<<<(NM1 * DD + 255) / 256, 256>>>(h, NM1 * DD);

    // gate logits (to output) + gumbel-softmax y
    k_gate<<<NM1, 128>>>(h, W2, b2, gu, out_gate, yv);

    // top-8 + z_hard output + selected frame indices
    k_topk<<<1, 32>>>(yv, out_z);

    // pooled features from the 9 selected frames only
    k_pool<<<NQk * 3, 128>>>(v, pooled);

    // thumbnail = pooled @ W_th + b_th   [64,1536]x[1536,4096]
    k_init_bias<<<(NQk * LMq + 255) / 256, 256>>>(out_thumb, b_th, NQk * LMq, LMq);
    {
        dim3 grid(LMq / 64, NQk / 64, 4);
        k_gemm_splitk<<<grid, 256>>>(pooled, W_th, out_thumb, NQk, LMq, DD, DD / 4);
    }
}